// round 14
// baseline (speedup 1.0000x reference)
#include <cuda_runtime.h>

// NeighborList: all i<j pairs, minimum-image PBC, cutoff mask. Single fused kernel.
// Output (float32): [0,P) pair_i | [P,2P) pair_j | [2P,5P) deltas[P,3] | [5P,6P) dist

#define TPB      256
#define KITER    4
#define BLKPAIRS (TPB * KITER)   // 1024 j's per block -> 12KB smem tile

__device__ __forceinline__ float fast_sqrt(float x) {
    float r;
    asm("sqrt.approx.f32 %0, %1;" : "=f"(r) : "f"(x));
    return r;
}

// Row-block mapping: blockIdx.y = row i; block covers BLKPAIRS consecutive j's.
// The block's j-atoms are staged once into a smem tile (coalesced copy); in-loop
// reads are conflict-free stride-3 LDS. No prep kernel, no device globals.
__global__ void __launch_bounds__(TPB)
nl_kernel(const float* __restrict__ xyz, const float* __restrict__ cell,
          float* __restrict__ out, int n, unsigned P) {
    const int i     = blockIdx.y;
    const int len   = n - 1 - i;                 // pairs in this row
    const int start = blockIdx.x * BLKPAIRS;     // offset within row
    if (start >= len) return;                    // empty block: fast exit

    const bool full = (start + BLKPAIRS) <= len; // uniform: interior block

    const unsigned T    = 2u * (unsigned)n - 1u;
    const unsigned offi = ((unsigned)i * (T - (unsigned)i)) >> 1;

    const int tid = threadIdx.x;

    // ---- stage this block's j-atoms (AoS floats) into smem, coalesced ----
    __shared__ float stile[3 * BLKPAIRS];
    {
        const int base = 3 * (i + 1 + start);    // first float index of tile
        const int lim  = 3 * n - 1;              // clamp (garbage ok, masked later)
#pragma unroll
        for (int q = 0; q < 3 * KITER; q++) {    // 12 iterations of TPB floats
            int gidx = base + q * TPB + tid;
            if (gidx > lim) gidx = lim;
            stile[q * TPB + tid] = xyz[gidx];
        }
    }
    __syncthreads();

    // ---- per-thread cell classification + diag constants (bit-identical
    //      to the adjugate-inverse: off-diagonal zeros vanish exactly) ----
    const float c0 = __ldg(&cell[0]), c1 = __ldg(&cell[1]), c2 = __ldg(&cell[2]);
    const float c3 = __ldg(&cell[3]), c4 = __ldg(&cell[4]), c5 = __ldg(&cell[5]);
    const float c6 = __ldg(&cell[6]), c7 = __ldg(&cell[7]), c8 = __ldg(&cell[8]);
    const bool zero = (c0 == 0.f) && (c1 == 0.f) && (c2 == 0.f) &&
                      (c3 == 0.f) && (c4 == 0.f) && (c5 == 0.f) &&
                      (c6 == 0.f) && (c7 == 0.f) && (c8 == 0.f);
    const bool offz = (c1 == 0.f) && (c2 == 0.f) && (c3 == 0.f) &&
                      (c5 == 0.f) && (c6 == 0.f) && (c7 == 0.f);
    const int general = (!zero && !offz) ? 1 : 0;

    float d0 = 0.f, d4 = 0.f, d8 = 0.f, e0 = 0.f, e4 = 0.f, e8 = 0.f;
    if (!zero && offz) {
        const float det = c0 * (c4 * c8);        // adjugate det reduces exactly
        const float invdet = 1.0f / det;
        d0 = (c4 * c8) * invdet;
        d4 = (c0 * c8) * invdet;
        d8 = (c0 * c4) * invdet;
        e0 = c0; e4 = c4; e8 = c8;
    }

    // row atom (uniform broadcast, L1-hit)
    const float xi = __ldg(&xyz[3 * i + 0]);
    const float yi = __ldg(&xyz[3 * i + 1]);
    const float zi = __ldg(&xyz[3 * i + 2]);
    const float fi = (float)i;

    int jo = start + tid;                        // pair offset within row
    const size_t p0 = (size_t)offi + (size_t)jo;
    float* pi = out + p0;
    float* pj = out + (size_t)P + p0;
    float* pd = out + 5 * (size_t)P + p0;
    float* db = out + 2 * (size_t)P + 3 * p0;
    int slj = 3 * tid;                           // smem index of this thread's j

#pragma unroll
    for (int k = 0; k < KITER; k++) {
        if (!full && jo >= len) break;           // tail block only
        const int j = i + 1 + jo;

        float dx = xi - stile[slj + 0];          // stride-3 LDS: conflict-free
        float dy = yi - stile[slj + 1];
        float dz = zi - stile[slj + 2];

        if (!general) {
            // diagonal (or no) PBC: per-axis wrap; zeros => exact no-op
            dx -= rintf(dx * d0) * e0;           // jnp.round = half-to-even = rintf
            dy -= rintf(dy * d4) * e4;
            dz -= rintf(dz * d8) * e8;
        } else {
            // rare general cell: recompute inverse per pair from volatile loads
            // (keeps it register-free across the hot loop)
            volatile const float* vc = cell;
            const float a = vc[0], b = vc[1], cc = vc[2];
            const float d = vc[3], e = vc[4], f  = vc[5];
            const float g = vc[6], h = vc[7], ii = vc[8];
            const float A =  (e * ii - f * h);
            const float B = -(d * ii - f * g);
            const float C =  (d * h - e * g);
            const float invdet = 1.0f / (a * A + b * B + cc * C);
            const float i0 = A * invdet, i1 = -(b * ii - cc * h) * invdet,
                        i2 = (b * f - cc * e) * invdet;
            const float i3 = B * invdet, i4 =  (a * ii - cc * g) * invdet,
                        i5 = -(a * f - cc * d) * invdet;
            const float i6 = C * invdet, i7 = -(a * h - b * g) * invdet,
                        i8 = (a * e - b * d) * invdet;
            const float f0 = dx * i0 + dy * i3 + dz * i6;
            const float f1 = dx * i1 + dy * i4 + dz * i7;
            const float f2 = dx * i2 + dy * i5 + dz * i8;
            const float r0 = rintf(f0);
            const float r1 = rintf(f1);
            const float r2 = rintf(f2);
            dx -= r0 * a  + r1 * d  + r2 * g;
            dy -= r0 * b  + r1 * e  + r2 * h;
            dz -= r0 * cc + r1 * f  + r2 * ii;
        }

        const float dist = fast_sqrt(dx * dx + dy * dy + dz * dz);
        const bool m = (dist <= 5.0f);

        *pi = m ? fi : -1.0f;
        *pj = m ? (float)j : -1.0f;
        *pd = m ? dist : 0.0f;
        db[0] = m ? dx : 0.0f;                   // lane-consecutive scalar stores
        db[1] = m ? dy : 0.0f;
        db[2] = m ? dz : 0.0f;

        pi += TPB; pj += TPB; pd += TPB; db += 3 * TPB;
        jo += TPB; slj += 3 * TPB;
    }
}

extern "C" void kernel_launch(void* const* d_in, const int* in_sizes, int n_in,
                              void* d_out, int out_size) {
    const float* xyz  = (const float*)d_in[0];
    const float* cell = (const float*)d_in[1];
    if (n_in >= 2 && in_sizes[0] == 9 && in_sizes[1] != 9) {
        const float* t = xyz; xyz = cell; cell = t;
    }
    const int n = (in_sizes[0] == 9 && n_in >= 2) ? in_sizes[1] / 3 : in_sizes[0] / 3;
    const unsigned P = (unsigned)((size_t)n * (size_t)(n - 1) / 2);

    const int maxlen = n - 1;
    dim3 grid((maxlen + BLKPAIRS - 1) / BLKPAIRS, n - 1);
    nl_kernel<<<grid, TPB>>>(xyz, cell, (float*)d_out, n, P);
}